// round 3
// baseline (speedup 1.0000x reference)
#include <cuda_runtime.h>

typedef unsigned long long ull;

// Problem constants
#define Bsz    32768
#define Tt     7
#define Ff     36
#define Uu     256
#define KK     292     // Uu + Ff total contraction length
#define MROW   296     // padded multiplier row (floats), 296*4 % 16 == 0
#define BM     32      // batch rows per CTA
#define NT     128     // 4 warps
#define RR     8       // rows per thread
#define TILE   8       // k-rows per weight tile
#define NTILES 37      // 36 tiles of 8 + 1 tile of 4 = 292
#define NBUF   3       // triple buffer

// ---------------------------------------------------------------------------
// helpers
// ---------------------------------------------------------------------------
__device__ __forceinline__ ull dup2(float a) {
    ull r; asm("mov.b64 %0, {%1, %1};" : "=l"(r) : "f"(a)); return r;
}
__device__ __forceinline__ void unpk(ull v, float& a, float& b) {
    asm("mov.b64 {%0, %1}, %2;" : "=f"(a), "=f"(b) : "l"(v));
}
__device__ __forceinline__ void ffma2(ull& d, ull a, ull b) {
    asm("fma.rn.f32x2 %0, %1, %2, %0;" : "+l"(d) : "l"(a), "l"(b));
}
// fast sigmoid / tanh via MUFU.EX2 + MUFU.RCP (err ~1e-7, tol 1e-3)
__device__ __forceinline__ float fsgm(float z) {
    float e, r;
    asm("ex2.approx.f32 %0, %1;" : "=f"(e) : "f"(-1.4426950408889634f * z));
    asm("rcp.approx.f32 %0, %1;" : "=f"(r) : "f"(1.0f + e));
    return r;
}
__device__ __forceinline__ float ftanh(float z) {
    float e, r;
    asm("ex2.approx.f32 %0, %1;" : "=f"(e) : "f"(-2.8853900817779268f * z));
    asm("rcp.approx.f32 %0, %1;" : "=f"(r) : "f"(1.0f + e));
    return fmaf(2.0f, r, -1.0f);
}
__device__ __forceinline__ void cp_async16(void* smem_dst, const void* gsrc) {
    unsigned s = (unsigned)__cvta_generic_to_shared(smem_dst);
    asm volatile("cp.async.cg.shared.global [%0], [%1], 16;" :: "r"(s), "l"(gsrc));
}
__device__ __forceinline__ void cp_commit() {
    asm volatile("cp.async.commit_group;" ::: "memory");
}
__device__ __forceinline__ void cp_wait1() {
    asm volatile("cp.async.wait_group 1;" ::: "memory");
}
__device__ __forceinline__ void cp_wait0() {
    asm volatile("cp.async.wait_group 0;" ::: "memory");
}

// ---------------------------------------------------------------------------
// stage one weight tile (TILE k-rows x 256 gate cols = 8KB) into wbuf[buf]
// tile i: k0 = 8*i; i<32 -> Wr rows, else Wk rows (k0-256). last tile: 4 rows.
// ---------------------------------------------------------------------------
__device__ __forceinline__ void copy_tile(
    int i, int buf, int gate, int tid,
    const float* __restrict__ Wr, const float* __restrict__ Wk,
    ull (*wbuf)[TILE][128])
{
    const int k0 = i * TILE;
    const float* src;
    int kb;
    if (k0 < Uu) { src = Wr; kb = k0; }
    else         { src = Wk; kb = k0 - Uu; }
    const int cnt = (KK - k0) < TILE ? (KK - k0) : TILE;   // 8 or 4
    const int units = cnt * 64;                            // 16B units
#pragma unroll 1
    for (int u = tid; u < units; u += NT) {
        int kk = u >> 6, ch = u & 63;
        const float* g = src + (size_t)(kb + kk) * 1024 + gate * 256 + ch * 4;
        cp_async16(&wbuf[buf][kk][ch * 2], g);
    }
    cp_commit();
}

// ---------------------------------------------------------------------------
// compute one tile: acc += m[:, k0:k0+cnt] @ W_tile
// lane tu owns gate cols 4tu..4tu+3 and 4(tu+32)..4(tu+32)+3
// ---------------------------------------------------------------------------
__device__ __forceinline__ void compute_tile(
    int i, int buf, int rbase, int tu,
    const float (*__restrict__ m)[MROW],
    const ull (*wbuf)[TILE][128],
    ull acc[RR][4])
{
    const int k0 = i * TILE;
    const int cnt = (KK - k0) < TILE ? (KK - k0) : TILE;   // 8 or 4 (mult of 4)
    const ull* wb = &wbuf[buf][0][0];
#pragma unroll 1
    for (int kq = 0; kq < cnt; kq += 4) {
        float4 m4[RR];
#pragma unroll
        for (int r = 0; r < RR; r++)
            m4[r] = *reinterpret_cast<const float4*>(&m[rbase + r][k0 + kq]);
#pragma unroll
        for (int kk = 0; kk < 4; kk++) {
            const ull* row = wb + (kq + kk) * 128;
            ulonglong2 wa = *reinterpret_cast<const ulonglong2*>(row + 2 * tu);
            ulonglong2 wv = *reinterpret_cast<const ulonglong2*>(row + 2 * (tu + 32));
#pragma unroll
            for (int r = 0; r < RR; r++) {
                float hv = reinterpret_cast<const float*>(&m4[r])[kk];
                ull h2 = dup2(hv);
                ffma2(acc[r][0], h2, wa.x);
                ffma2(acc[r][1], h2, wa.y);
                ffma2(acc[r][2], h2, wv.x);
                ffma2(acc[r][3], h2, wv.y);
            }
        }
    }
}

// ---------------------------------------------------------------------------
// full gate pass with cp.async pipeline
// ---------------------------------------------------------------------------
__device__ __forceinline__ void gate_pass(
    int gate, int rbase, int tu, int tid,
    const float* __restrict__ Wr, const float* __restrict__ Wk,
    const ulonglong2* __restrict__ b2,
    const float (*__restrict__ m)[MROW],
    ull (*wbuf)[TILE][128],
    ull acc[RR][4])
{
    // init accumulators with bias
    ulonglong2 ba = b2[gate * 64 + tu];
    ulonglong2 bb = b2[gate * 64 + tu + 32];
#pragma unroll
    for (int r = 0; r < RR; r++) {
        acc[r][0] = ba.x; acc[r][1] = ba.y;
        acc[r][2] = bb.x; acc[r][3] = bb.y;
    }

    // wbuf is shared across gates: previous gate's last compute must be done
    __syncthreads();

    copy_tile(0, 0, gate, tid, Wr, Wk, wbuf);
    copy_tile(1, 1, gate, tid, Wr, Wk, wbuf);

#pragma unroll 1
    for (int i = 0; i < NTILES; i++) {
        if (i + 1 < NTILES) cp_wait1(); else cp_wait0();
        __syncthreads();
        if (i + 2 < NTILES) copy_tile(i + 2, (i + 2) % NBUF, gate, tid, Wr, Wk, wbuf);
        compute_tile(i, i % NBUF, rbase, tu, m, wbuf, acc);
    }
}

// ---------------------------------------------------------------------------
// LSTM kernel: one CTA = 32 batch rows; 2 CTAs per SM.
// ---------------------------------------------------------------------------
__global__ void __launch_bounds__(NT, 2)
lstm_kernel(const float* __restrict__ x,   // [B,T,F]
            const float* __restrict__ h0,  // [B,U]
            const float* __restrict__ c0,  // [B,U]
            const float* __restrict__ Wk,  // [F,4U]
            const float* __restrict__ Wr,  // [U,4U]
            const float* __restrict__ b,   // [4U]
            float* __restrict__ out)       // [B,T,U]
{
    __shared__ float m_sh[BM][MROW];          // 37.9 KB: h | x_t
    __shared__ float c_sh[BM][Uu];            // 32 KB
    __shared__ ull   wbuf[NBUF][TILE][128];   // 24 KB weight tiles

    const int tid   = threadIdx.x;
    const int tu    = tid & 31;
    const int w     = tid >> 5;
    const int rbase = w * RR;
    const int row0  = blockIdx.x * BM;

    // ---- stage h0 -> m_sh[:, 0:256], c0 -> c_sh (float4 coalesced) ----
    {
        const float4* hsrc = reinterpret_cast<const float4*>(h0 + (size_t)row0 * Uu);
        const float4* csrc = reinterpret_cast<const float4*>(c0 + (size_t)row0 * Uu);
#pragma unroll 1
        for (int i = tid; i < BM * Uu / 4; i += NT) {
            int r = i >> 6, cq = i & 63;
            *reinterpret_cast<float4*>(&m_sh[r][cq * 4]) = hsrc[i];
            *reinterpret_cast<float4*>(&c_sh[r][cq * 4]) = csrc[i];
        }
    }

    const ulonglong2* __restrict__ b2 = reinterpret_cast<const ulonglong2*>(b);
    float4* __restrict__ out4 = reinterpret_cast<float4*>(out);

    float gv[RR][8];
    ull acc[RR][4];

#pragma unroll 1
    for (int t = 0; t < Tt; t++) {
        // ---- load x_t for this warp's rows -> m_sh[:, 256:292] ----
#pragma unroll 1
        for (int idx = tu; idx < RR * Ff; idx += 32) {
            int r = idx / Ff, f = idx - r * Ff;
            m_sh[rbase + r][Uu + f] =
                x[((size_t)(row0 + rbase + r) * Tt + t) * Ff + f];
        }
        // visibility handled by the __syncthreads inside gate_pass

        // ---- gate g (gsel=2): gv = tanh(z_g) ----
        gate_pass(2, rbase, tu, tid, Wr, Wk, b2, m_sh, wbuf, acc);
#pragma unroll
        for (int r = 0; r < RR; r++)
#pragma unroll
            for (int j = 0; j < 4; j++) {
                float z0, z1; unpk(acc[r][j], z0, z1);
                gv[r][2 * j]     = ftanh(z0);
                gv[r][2 * j + 1] = ftanh(z1);
            }

        // ---- gate i (gsel=0): gv *= sigmoid(z_i) ----
        gate_pass(0, rbase, tu, tid, Wr, Wk, b2, m_sh, wbuf, acc);
#pragma unroll
        for (int r = 0; r < RR; r++)
#pragma unroll
            for (int j = 0; j < 4; j++) {
                float z0, z1; unpk(acc[r][j], z0, z1);
                gv[r][2 * j]     *= fsgm(z0);
                gv[r][2 * j + 1] *= fsgm(z1);
            }

        // ---- gate f (gsel=1): c = sigmoid(z_f)*c + gv ; gv = tanh(c) ----
        gate_pass(1, rbase, tu, tid, Wr, Wk, b2, m_sh, wbuf, acc);
#pragma unroll
        for (int r = 0; r < RR; r++) {
            const int rr = rbase + r;
            float4 cA = *reinterpret_cast<float4*>(&c_sh[rr][4 * tu]);
            float4 cB = *reinterpret_cast<float4*>(&c_sh[rr][4 * (tu + 32)]);
            float z0, z1;
            unpk(acc[r][0], z0, z1);
            cA.x = fsgm(z0) * cA.x + gv[r][0];
            cA.y = fsgm(z1) * cA.y + gv[r][1];
            unpk(acc[r][1], z0, z1);
            cA.z = fsgm(z0) * cA.z + gv[r][2];
            cA.w = fsgm(z1) * cA.w + gv[r][3];
            unpk(acc[r][2], z0, z1);
            cB.x = fsgm(z0) * cB.x + gv[r][4];
            cB.y = fsgm(z1) * cB.y + gv[r][5];
            unpk(acc[r][3], z0, z1);
            cB.z = fsgm(z0) * cB.z + gv[r][6];
            cB.w = fsgm(z1) * cB.w + gv[r][7];
            *reinterpret_cast<float4*>(&c_sh[rr][4 * tu])        = cA;
            *reinterpret_cast<float4*>(&c_sh[rr][4 * (tu + 32)]) = cB;
            gv[r][0] = ftanh(cA.x); gv[r][1] = ftanh(cA.y);
            gv[r][2] = ftanh(cA.z); gv[r][3] = ftanh(cA.w);
            gv[r][4] = ftanh(cB.x); gv[r][5] = ftanh(cB.y);
            gv[r][6] = ftanh(cB.z); gv[r][7] = ftanh(cB.w);
        }

        // ---- gate o (gsel=3): h = sigmoid(z_o) * gv ----
        gate_pass(3, rbase, tu, tid, Wr, Wk, b2, m_sh, wbuf, acc);
#pragma unroll
        for (int r = 0; r < RR; r++)
#pragma unroll
            for (int j = 0; j < 4; j++) {
                float z0, z1; unpk(acc[r][j], z0, z1);
                gv[r][2 * j]     *= fsgm(z0);
                gv[r][2 * j + 1] *= fsgm(z1);
            }

        // ---- publish h_new to m_sh (own rows; next sync is in gate_pass)
        //      and stream result to out ----
#pragma unroll
        for (int r = 0; r < RR; r++) {
            const int rr = rbase + r;
            float4 hA = make_float4(gv[r][0], gv[r][1], gv[r][2], gv[r][3]);
            float4 hB = make_float4(gv[r][4], gv[r][5], gv[r][6], gv[r][7]);
            *reinterpret_cast<float4*>(&m_sh[rr][4 * tu])        = hA;
            *reinterpret_cast<float4*>(&m_sh[rr][4 * (tu + 32)]) = hB;
            size_t ob = ((size_t)(row0 + rr) * Tt + t) * 64;
            out4[ob + tu]      = hA;
            out4[ob + tu + 32] = hB;
        }
        __syncwarp();
    }
}

// ---------------------------------------------------------------------------
// Harness entry point
// ---------------------------------------------------------------------------
extern "C" void kernel_launch(void* const* d_in, const int* in_sizes, int n_in,
                              void* d_out, int out_size) {
    const float* x  = (const float*)d_in[0];  // [B,T,F]
    const float* h0 = (const float*)d_in[1];  // [B,U]
    const float* c0 = (const float*)d_in[2];  // [B,U]
    const float* Wk = (const float*)d_in[3];  // [F,4U]
    const float* Wr = (const float*)d_in[4];  // [U,4U]
    const float* b  = (const float*)d_in[5];  // [4U]
    float* out = (float*)d_out;               // [B,T,U]

    lstm_kernel<<<Bsz / BM, NT>>>(x, h0, c0, Wk, Wr, b, out);
}